// round 1
// baseline (speedup 1.0000x reference)
#include <cuda_runtime.h>
#include <math.h>

// Shapes
#define BSZ   2048
#define IN    128
#define ON    128
#define DN    2
#define GN    8
#define NN    256            // O*D
#define KTOT  8192           // I*G*G
#define SPLIT 8
#define IPS   (IN / SPLIT)   // 16 i's per k-slice
#define BPC   8              // b-rows per combine CTA
#define NCOMB (BSZ / BPC)    // 256 combine CTAs

// Scratch (static device arrays -- no allocation)
__device__ float g_part[SPLIT][BSZ][NN];   // 16 MB split-K partials
__device__ float g_pre[BSZ][NN];           // pre-BN output
__device__ float g_sbsum[NN];              // sum_i silu_bias
__device__ float g_bstat[NCOMB][4];        // per-CTA {sum0,sum1,sq0,sq1}
__device__ float g_stats[4];               // {scale0,scale1,shift0,shift1}

// Shared memory layout for k_main: As[64][132] + Bs[64][132] + gu[8] + gv[8]
#define SROW 132
#define SMEM_MAIN ((2 * 64 * SROW + 16) * 4)

// ---------------------------------------------------------------------------
// Main split-K GEMM: out_part[s][b][n] = sum_{k in slice s} A[b,k] * W[k,n]
// A[b,(i,u,v)] = exp(-(xr-gu)^2) * exp(-(xi-gv)^2)  (generated on the fly)
// CTA tile 128(M) x 128(N), 256 threads, 8x8 microtile, k-tile = 64 (one i).
// ---------------------------------------------------------------------------
__global__ __launch_bounds__(256, 2)
void k_main(const float* __restrict__ x, const float* __restrict__ w,
            const float* __restrict__ grd) {
    extern __shared__ float sm[];
    float* As = sm;                    // [64][SROW], k-major, index by m
    float* Bs = sm + 64 * SROW;        // [64][SROW], k-major, index by n
    float* gS = sm + 2 * 64 * SROW;    // gu[8], gv[8]

    const int tid = threadIdx.x;
    const int bm  = blockIdx.x * 128;
    const int o0  = blockIdx.y * 64;       // 64 output heads per n-tile
    const int i0  = blockIdx.z * IPS;

    if (tid < 8) {
        gS[tid]     = grd[tid * 16];       // g[u] = grid[u][0][0]
        gS[8 + tid] = grd[tid * 2 + 1];    // g[v] = grid[0][v][1]
    }

    const int ty = tid >> 4, tx = tid & 15;
    const int m0 = ty * 4;      // rows m0..m0+3 and m0+64..m0+67
    const int n0 = tx * 4;      // cols n0..n0+3 and n0+64..n0+67

    float acc[8][8];
#pragma unroll
    for (int p = 0; p < 8; p++)
#pragma unroll
        for (int q = 0; q < 8; q++) acc[p][q] = 0.f;

    const int am    = tid >> 1;            // m-row this thread fills in As
    const int kbase = (tid & 1) * 32;      // which half of k it fills
    const float* xp = x + (size_t)(bm + am) * (IN * DN);

    __syncthreads();   // gS visible

    for (int ii = 0; ii < IPS; ii++) {
        const int i = i0 + ii;
        // ---- fill As[k][m]: separable RBF ----
        {
            float xr = xp[i * 2], xi = xp[i * 2 + 1];
            float eur[8], evr[8];
#pragma unroll
            for (int u = 0; u < 8; u++) {
                float d = xr - gS[u];      eur[u] = __expf(-d * d);
                float e = xi - gS[8 + u];  evr[u] = __expf(-e * e);
            }
#pragma unroll
            for (int kk = 0; kk < 32; kk++) {
                int k = kbase + kk;
                As[k * SROW + am] = eur[k >> 3] * evr[k & 7];
            }
        }
        // ---- fill Bs[k][n]: transpose weights (i,o,u,v,x) -> [k=(u,v)][n=(o,x)] ----
        {
            const float* wp = w + (size_t)i * (ON * GN * GN * DN) + (size_t)o0 * 128;
#pragma unroll
            for (int j = 0; j < 8; j++) {
                int f  = tid + j * 256;          // float4 index in [0, 2048)
                int oo = f >> 5;                 // local o (0..63)
                int t  = (f & 31) * 4;           // offset in the 128-float o-row
                float4 v4 = *(const float4*)(wp + oo * 128 + t);
                float vv[4] = {v4.x, v4.y, v4.z, v4.w};
#pragma unroll
                for (int e = 0; e < 4; e++) {
                    int te = t + e;                       // u*16 + v*2 + x
                    int k  = ((te >> 4) << 3) | ((te >> 1) & 7);
                    Bs[k * SROW + oo * 2 + (te & 1)] = vv[e];
                }
            }
        }
        __syncthreads();
        // ---- 128x128x64 FMA mainloop ----
#pragma unroll 8
        for (int k = 0; k < 64; k++) {
            float a[8], b[8];
            *(float4*)&a[0] = *(const float4*)&As[k * SROW + m0];
            *(float4*)&a[4] = *(const float4*)&As[k * SROW + m0 + 64];
            *(float4*)&b[0] = *(const float4*)&Bs[k * SROW + n0];
            *(float4*)&b[4] = *(const float4*)&Bs[k * SROW + n0 + 64];
#pragma unroll
            for (int p = 0; p < 8; p++)
#pragma unroll
                for (int q = 0; q < 8; q++)
                    acc[p][q] += a[p] * b[q];
        }
        __syncthreads();
    }

    // ---- epilogue: write partials ----
#pragma unroll
    for (int p = 0; p < 8; p++) {
        int m = bm + ((p < 4) ? (m0 + p) : (m0 + 60 + p));  // +64 block for p>=4
        float* row = &g_part[blockIdx.z][m][o0 * 2];
        *(float4*)(row + n0)      = make_float4(acc[p][0], acc[p][1], acc[p][2], acc[p][3]);
        *(float4*)(row + n0 + 64) = make_float4(acc[p][4], acc[p][5], acc[p][6], acc[p][7]);
    }
}

// ---------------------------------------------------------------------------
// sum_i silu_bias[i][n]
// ---------------------------------------------------------------------------
__global__ void k_sbsum(const float* __restrict__ sb) {
    int n = threadIdx.x;
    float s = 0.f;
    for (int i = 0; i < IN; i++) s += sb[i * NN + n];
    g_sbsum[n] = s;
}

// ---------------------------------------------------------------------------
// Combine: pre[b][n] = sum_s part[s][b][n] + sbsum[n]
//                      + sum_i (Cayley complex product of silu_weight and silu(x))
// Also emits per-CTA BN partial sums (deterministic).
// ---------------------------------------------------------------------------
__global__ __launch_bounds__(256)
void k_combine(const float* __restrict__ x, const float* __restrict__ sw,
               const float* __restrict__ cay) {
    __shared__ float sS[BPC][IN * DN];   // silu(x) staged, 8 KB
    __shared__ float rs[256], rq[256];
    const int tid = threadIdx.x;
    const int b0  = blockIdx.x * BPC;

    for (int idx = tid; idx < BPC * IN * DN; idx += 256) {
        int bb = idx >> 8, r = idx & 255;
        float v = x[(size_t)(b0 + bb) * (IN * DN) + r];
        sS[bb][r] = v / (1.f + __expf(-v));
    }
    __syncthreads();

    const int n = tid, z = n & 1;
    // C[x][y][z] at x*4 + y*2 + z
    const float c00 = cay[z], c01 = cay[2 + z], c10 = cay[4 + z], c11 = cay[6 + z];

    float acc[BPC];
    float base = g_sbsum[n];
#pragma unroll
    for (int bb = 0; bb < BPC; bb++) acc[bb] = base;

    for (int i = 0; i < IN; i++) {
        float2 w2 = *(const float2*)(sw + i * NN + (n & ~1));
        float t0 = w2.x * c00 + w2.y * c10;   // multiplies s0
        float t1 = w2.x * c01 + w2.y * c11;   // multiplies s1
#pragma unroll
        for (int bb = 0; bb < BPC; bb++) {
            float s0 = sS[bb][i * 2], s1 = sS[bb][i * 2 + 1];
            acc[bb] += t0 * s0 + t1 * s1;
        }
    }

    float lsum = 0.f, lsq = 0.f;
#pragma unroll
    for (int bb = 0; bb < BPC; bb++) {
        float v = acc[bb];
#pragma unroll
        for (int s2 = 0; s2 < SPLIT; s2++) v += g_part[s2][b0 + bb][n];
        g_pre[b0 + bb][n] = v;
        lsum += v; lsq += v * v;
    }
    rs[tid] = lsum; rq[tid] = lsq;
    __syncthreads();
    // parity-preserving tree reduce (strides all even until 2)
    for (int st = 128; st >= 2; st >>= 1) {
        if (tid < st) { rs[tid] += rs[tid + st]; rq[tid] += rq[tid + st]; }
        __syncthreads();
    }
    if (tid < 2) {
        g_bstat[blockIdx.x][tid]     = rs[tid];
        g_bstat[blockIdx.x][2 + tid] = rq[tid];
    }
}

// ---------------------------------------------------------------------------
// Final BN stats from per-CTA partials (deterministic single-CTA reduce)
// ---------------------------------------------------------------------------
__global__ void k_stats(const float* __restrict__ gamma, const float* __restrict__ beta) {
    __shared__ float r[4][256];
    const int tid = threadIdx.x;
#pragma unroll
    for (int j = 0; j < 4; j++) r[j][tid] = g_bstat[tid][j];
    __syncthreads();
    for (int st = 128; st >= 1; st >>= 1) {
        if (tid < st) {
#pragma unroll
            for (int j = 0; j < 4; j++) r[j][tid] += r[j][tid + st];
        }
        __syncthreads();
    }
    if (tid < 2) {
        const float Ninv = 1.f / (2048.f * 128.f);
        float mean = r[tid][0] * Ninv;
        float var  = r[2 + tid][0] * Ninv - mean * mean;
        float sc   = gamma[tid] * rsqrtf(var + 1e-5f);
        g_stats[tid]     = sc;
        g_stats[2 + tid] = beta[tid] - mean * sc;
    }
}

// ---------------------------------------------------------------------------
// Normalize -> d_out
// ---------------------------------------------------------------------------
__global__ __launch_bounds__(256)
void k_norm(float* __restrict__ out) {
    int idx = blockIdx.x * 256 + threadIdx.x;      // float4 index, 131072 total
    float s0 = g_stats[0], s1 = g_stats[1], h0 = g_stats[2], h1 = g_stats[3];
    float4 v = *(((const float4*)&g_pre[0][0]) + idx);
    v.x = v.x * s0 + h0;
    v.y = v.y * s1 + h1;
    v.z = v.z * s0 + h0;
    v.w = v.w * s1 + h1;
    ((float4*)out)[idx] = v;
}

// ---------------------------------------------------------------------------
extern "C" void kernel_launch(void* const* d_in, const int* in_sizes, int n_in,
                              void* d_out, int out_size) {
    const float* x     = (const float*)d_in[0];
    const float* w     = (const float*)d_in[1];
    const float* sw    = (const float*)d_in[2];
    const float* sb    = (const float*)d_in[3];
    const float* gamma = (const float*)d_in[4];
    const float* beta  = (const float*)d_in[5];
    const float* grd   = (const float*)d_in[6];
    const float* cay   = (const float*)d_in[7];
    float* out = (float*)d_out;

    cudaFuncSetAttribute(k_main, cudaFuncAttributeMaxDynamicSharedMemorySize, SMEM_MAIN);

    k_sbsum<<<1, 256>>>(sb);
    k_main<<<dim3(16, 2, SPLIT), 256, SMEM_MAIN>>>(x, w, grd);
    k_combine<<<NCOMB, 256>>>(x, sw, cay);
    k_stats<<<1, 256>>>(gamma, beta);
    k_norm<<<512, 256>>>(out);
}

// round 3
// speedup vs baseline: 3.1419x; 3.1419x over previous
#include <cuda_runtime.h>
#include <cuda_bf16.h>
#include <cstdint>
#include <math.h>

// Shapes
#define BSZ   2048
#define IN    128
#define ON    128
#define DN    2
#define NN    256            // O*D
#define SPLIT 4
#define IPS   (IN / SPLIT)   // 32 i's per k-slice
#define BPC   8
#define NCOMB (BSZ / BPC)

// Scratch (static device arrays -- no allocation)
__device__ float g_part[SPLIT][BSZ][NN];       // 8 MB split-K partials
__device__ float g_pre[BSZ][NN];
__device__ float g_sbsum[NN];
__device__ float g_bstat[NCOMB][4];
__device__ float g_stats[4];
__device__ __nv_bfloat16 g_whi[IN * NN * 64];  // 4 MB, [i][n=(o,x)][k=(u,v)]
__device__ __nv_bfloat16 g_wlo[IN * NN * 64];  // 4 MB

// ---------------------------------------------------------------------------
// PTX helpers (sm_80-class ISA only: ldmatrix / mma.sync / cp.async)
// ---------------------------------------------------------------------------
__device__ __forceinline__ uint32_t smem_u32(const void* p) {
    uint32_t a;
    asm("{ .reg .u64 t; cvta.to.shared.u64 t, %1; cvt.u32.u64 %0, t; }" : "=r"(a) : "l"(p));
    return a;
}
__device__ __forceinline__ void ldsm_x4(uint32_t* r, uint32_t addr) {
    asm volatile("ldmatrix.sync.aligned.m8n8.x4.shared.b16 {%0,%1,%2,%3}, [%4];"
                 : "=r"(r[0]), "=r"(r[1]), "=r"(r[2]), "=r"(r[3]) : "r"(addr));
}
__device__ __forceinline__ void mma_bf16(float* c, const uint32_t* a, const uint32_t* b) {
    asm volatile(
        "mma.sync.aligned.m16n8k16.row.col.f32.bf16.bf16.f32 "
        "{%0,%1,%2,%3}, {%4,%5,%6,%7}, {%8,%9}, {%0,%1,%2,%3};"
        : "+f"(c[0]), "+f"(c[1]), "+f"(c[2]), "+f"(c[3])
        : "r"(a[0]), "r"(a[1]), "r"(a[2]), "r"(a[3]), "r"(b[0]), "r"(b[1]));
}
#define CP_ASYNC16(dst, src) asm volatile("cp.async.cg.shared.global [%0], [%1], 16;" :: "r"(dst), "l"(src) : "memory")
#define CP_COMMIT()          asm volatile("cp.async.commit_group;" ::: "memory")
#define CP_WAIT(n)           asm volatile("cp.async.wait_group %0;" :: "n"(n) : "memory")

// smem tile geometry: rows padded to 72 bf16 (144 B) for conflict-free ldmatrix
#define RPAD   72
#define MAT_SZ (128 * RPAD * 2)            // 18432 B per matrix
#define A_HI   0
#define A_LO   (MAT_SZ)
#define B_HI   (2 * MAT_SZ)
#define B_LO   (3 * MAT_SZ)
#define BUF_SZ (4 * MAT_SZ)                // 73728 B
#define SMEM_TC (2 * BUF_SZ)               // 147456 B

// ---------------------------------------------------------------------------
// Prep: split weights into bf16 hi/lo in MMA layout [i][n=(o*2+x)][k=(u*8+v)]
// ---------------------------------------------------------------------------
__global__ void k_prep(const float* __restrict__ w) {
    int idx = blockIdx.x * 256 + threadIdx.x;      // 0 .. 2M-1
    int i = idx >> 14;
    int n = (idx >> 6) & 255;
    int k = idx & 63;
    int o = n >> 1, xx = n & 1, u = k >> 3, v = k & 7;
    float a = w[((((size_t)i * 128 + o) * 8 + u) * 8 + v) * 2 + xx];
    __nv_bfloat16 h = __float2bfloat16(a);
    g_whi[idx] = h;
    g_wlo[idx] = __float2bfloat16(a - __bfloat162float(h));
}

// ---------------------------------------------------------------------------
// Tensor-core split-K GEMM via mma.sync (HMMA). grid (16, 2, SPLIT):
// CTA tile 128(M) x 128(N), K-slice = 32 i's, K=64 per i.
// A generated on the fly (separable RBF) -> bf16 hi/lo in smem.
// 3-pass split per k-step: ah*bh + al*bh + ah*bl. cp.async double-buffered B.
// 8 warps: warp tile 32(M) x 64(N).
// ---------------------------------------------------------------------------
__global__ __launch_bounds__(256)
void k_tc(const float* __restrict__ x, const float* __restrict__ grd) {
    extern __shared__ char smdyn[];
    __shared__ float gS[16];

    const int tid = threadIdx.x;
    const int wid = tid >> 5, lid = tid & 31;
    const int bm = blockIdx.x * 128;
    const int n0 = blockIdx.y * 128;       // global n offset of this CTA
    const int i0 = blockIdx.z * IPS;

    if (tid < 8) {
        gS[tid]     = grd[tid * 16];       // g[u] (real axis)
        gS[8 + tid] = grd[tid * 2 + 1];    // g[v] (imag axis)
    }

    const uint32_t sbase = smem_u32(smdyn);

    // warp layout: wm = wid>>1 (4), wn = wid&1 (2)
    const int wm = wid >> 1, wn = wid & 1;
    const int R = wm * 32;                 // warp row base within tile
    const int C = wn * 64;                 // warp col base within tile

    float acc[2][8][4];
#pragma unroll
    for (int t = 0; t < 2; t++)
#pragma unroll
        for (int j = 0; j < 8; j++)
#pragma unroll
            for (int e = 0; e < 4; e++) acc[t][j][e] = 0.f;

    // A-fill assignment: row am, half u0
    const int am = tid >> 1;
    const int u0 = (tid & 1) * 4;
    const float* xrow = x + (size_t)(bm + am) * (IN * DN);

    // B cp.async assignment: 1024 chunks/matrix, 4 per thread per matrix
    // chunk ch -> row n=ch>>3, koff=(ch&7)*16 bytes
    // prefetch B for i0 into buffer 0
    {
        const __nv_bfloat16* sH = g_whi + ((size_t)i0 * NN + n0) * 64;
        const __nv_bfloat16* sL = g_wlo + ((size_t)i0 * NN + n0) * 64;
#pragma unroll
        for (int c = 0; c < 4; c++) {
            int ch = tid + c * 256;
            uint32_t dst = (uint32_t)((ch >> 3) * (RPAD * 2) + (ch & 7) * 16);
            CP_ASYNC16(sbase + B_HI + dst, (const char*)sH + ch * 16);
            CP_ASYNC16(sbase + B_LO + dst, (const char*)sL + ch * 16);
        }
        CP_COMMIT();
    }
    __syncthreads();   // gS visible

    for (int ii = 0; ii < IPS; ii++) {
        const int i = i0 + ii;
        const uint32_t buf = sbase + (uint32_t)(ii & 1) * BUF_SZ;
        const uint32_t nbuf = sbase + (uint32_t)((ii + 1) & 1) * BUF_SZ;

        // ---- A fill into current buffer (separable RBF, bf16 hi/lo) ----
        {
            float xr = xrow[i * 2], xi = xrow[i * 2 + 1];
            float evr[8], eur[4];
#pragma unroll
            for (int v = 0; v < 8; v++) { float d = xi - gS[8 + v]; evr[v] = __expf(-d * d); }
#pragma unroll
            for (int uu = 0; uu < 4; uu++) { float d = xr - gS[u0 + uu]; eur[uu] = __expf(-d * d); }
            char* bufp = smdyn + (buf - sbase);
#pragma unroll
            for (int uu = 0; uu < 4; uu++) {
                union { __nv_bfloat16 b[8]; uint4 v; } Hi, Lo;
#pragma unroll
                for (int v = 0; v < 8; v++) {
                    float a = eur[uu] * evr[v];
                    __nv_bfloat16 h = __float2bfloat16(a);
                    Hi.b[v] = h;
                    Lo.b[v] = __float2bfloat16(a - __bfloat162float(h));
                }
                uint32_t off = (uint32_t)(am * (RPAD * 2) + (u0 + uu) * 16);
                *(uint4*)(bufp + A_HI + off) = Hi.v;
                *(uint4*)(bufp + A_LO + off) = Lo.v;
            }
        }
        // ---- prefetch next B into other buffer ----
        if (ii + 1 < IPS) {
            const __nv_bfloat16* sH = g_whi + ((size_t)(i + 1) * NN + n0) * 64;
            const __nv_bfloat16* sL = g_wlo + ((size_t)(i + 1) * NN + n0) * 64;
#pragma unroll
            for (int c = 0; c < 4; c++) {
                int ch = tid + c * 256;
                uint32_t dst = (uint32_t)((ch >> 3) * (RPAD * 2) + (ch & 7) * 16);
                CP_ASYNC16(nbuf + B_HI + dst, (const char*)sH + ch * 16);
                CP_ASYNC16(nbuf + B_LO + dst, (const char*)sL + ch * 16);
            }
            CP_COMMIT();
            CP_WAIT(1);   // current buffer's B done; next may fly
        } else {
            CP_WAIT(0);
        }
        __syncthreads();

        // ---- MMA over K=64: 4 k-steps, 3 split passes fused per step ----
#pragma unroll
        for (int ks = 0; ks < 4; ks++) {
            // A frags: 2 m16 tiles, hi + lo
            uint32_t ah[2][4], al[2][4];
#pragma unroll
            for (int t = 0; t < 2; t++) {
                int row = R + t * 16 + (lid & 15);
                uint32_t cb = (uint32_t)(ks * 32 + (lid >> 4) * 16);
                uint32_t aoff = (uint32_t)(row * (RPAD * 2)) + cb;
                ldsm_x4(ah[t], buf + A_HI + aoff);
                ldsm_x4(al[t], buf + A_LO + aoff);
            }
            // B frags: 8 n8 tiles in 4 x4-loads (2 tiles each)
#pragma unroll
            for (int jj = 0; jj < 4; jj++) {
                int nrow = C + jj * 16 + ((lid >> 4) * 8) + (lid & 7);
                uint32_t cb = (uint32_t)(ks * 32 + ((lid >> 3) & 1) * 16);
                uint32_t boff = (uint32_t)(nrow * (RPAD * 2)) + cb;
                uint32_t bh[4], bl[4];
                ldsm_x4(bh, buf + B_HI + boff);
                ldsm_x4(bl, buf + B_LO + boff);
#pragma unroll
                for (int t = 0; t < 2; t++) {
                    mma_bf16(acc[t][jj * 2],     ah[t], bh);
                    mma_bf16(acc[t][jj * 2],     al[t], bh);
                    mma_bf16(acc[t][jj * 2],     ah[t], bl);
                    mma_bf16(acc[t][jj * 2 + 1], ah[t], bh + 2);
                    mma_bf16(acc[t][jj * 2 + 1], al[t], bh + 2);
                    mma_bf16(acc[t][jj * 2 + 1], ah[t], bl + 2);
                }
            }
        }
        __syncthreads();
    }

    // ---- epilogue: direct register -> global partials ----
#pragma unroll
    for (int t = 0; t < 2; t++) {
#pragma unroll
        for (int j = 0; j < 8; j++) {
            int row = bm + R + t * 16 + (lid >> 2);
            int col = n0 + C + j * 8 + (lid & 3) * 2;
            float* p0 = &g_part[blockIdx.z][row][col];
            float* p1 = &g_part[blockIdx.z][row + 8][col];
            *(float2*)p0 = make_float2(acc[t][j][0], acc[t][j][1]);
            *(float2*)p1 = make_float2(acc[t][j][2], acc[t][j][3]);
        }
    }
}

// ---------------------------------------------------------------------------
// sum_i silu_bias[i][n]
// ---------------------------------------------------------------------------
__global__ void k_sbsum(const float* __restrict__ sb) {
    int n = threadIdx.x;
    float s = 0.f;
    for (int i = 0; i < IN; i++) s += sb[i * NN + n];
    g_sbsum[n] = s;
}

// ---------------------------------------------------------------------------
// Combine: pre = sum_s part + silu branch; emits BN partials (deterministic)
// ---------------------------------------------------------------------------
__global__ __launch_bounds__(256)
void k_combine(const float* __restrict__ x, const float* __restrict__ sw,
               const float* __restrict__ cay) {
    __shared__ float sS[BPC][IN * DN];
    __shared__ float rs[256], rq[256];
    const int tid = threadIdx.x;
    const int b0 = blockIdx.x * BPC;

    for (int idx = tid; idx < BPC * IN * DN; idx += 256) {
        int bb = idx >> 8, r = idx & 255;
        float v = x[(size_t)(b0 + bb) * (IN * DN) + r];
        sS[bb][r] = v / (1.f + __expf(-v));
    }
    __syncthreads();

    const int n = tid, z = n & 1;
    const float c00 = cay[z], c01 = cay[2 + z], c10 = cay[4 + z], c11 = cay[6 + z];

    float acc[BPC];
    float basev = g_sbsum[n];
#pragma unroll
    for (int bb = 0; bb < BPC; bb++) acc[bb] = basev;

    for (int i = 0; i < IN; i++) {
        float2 w2 = *(const float2*)(sw + i * NN + (n & ~1));
        float t0 = w2.x * c00 + w2.y * c10;
        float t1 = w2.x * c01 + w2.y * c11;
#pragma unroll
        for (int bb = 0; bb < BPC; bb++)
            acc[bb] += t0 * sS[bb][i * 2] + t1 * sS[bb][i * 2 + 1];
    }

    float lsum = 0.f, lsq = 0.f;
#pragma unroll
    for (int bb = 0; bb < BPC; bb++) {
        float v = acc[bb];
#pragma unroll
        for (int s2 = 0; s2 < SPLIT; s2++) v += g_part[s2][b0 + bb][n];
        g_pre[b0 + bb][n] = v;
        lsum += v; lsq += v * v;
    }
    rs[tid] = lsum; rq[tid] = lsq;
    __syncthreads();
    for (int st = 128; st >= 2; st >>= 1) {
        if (tid < st) { rs[tid] += rs[tid + st]; rq[tid] += rq[tid + st]; }
        __syncthreads();
    }
    if (tid < 2) {
        g_bstat[blockIdx.x][tid]     = rs[tid];
        g_bstat[blockIdx.x][2 + tid] = rq[tid];
    }
}

__global__ void k_stats(const float* __restrict__ gamma, const float* __restrict__ beta) {
    __shared__ float r[4][256];
    const int tid = threadIdx.x;
#pragma unroll
    for (int j = 0; j < 4; j++) r[j][tid] = g_bstat[tid][j];
    __syncthreads();
    for (int st = 128; st >= 1; st >>= 1) {
        if (tid < st) {
#pragma unroll
            for (int j = 0; j < 4; j++) r[j][tid] += r[j][tid + st];
        }
        __syncthreads();
    }
    if (tid < 2) {
        const float Ninv = 1.f / (2048.f * 128.f);
        float mean = r[tid][0] * Ninv;
        float var  = r[2 + tid][0] * Ninv - mean * mean;
        float sc   = gamma[tid] * rsqrtf(var + 1e-5f);
        g_stats[tid]     = sc;
        g_stats[2 + tid] = beta[tid] - mean * sc;
    }
}

__global__ __launch_bounds__(256)
void k_norm(float* __restrict__ out) {
    int idx = blockIdx.x * 256 + threadIdx.x;
    float s0 = g_stats[0], s1 = g_stats[1], h0 = g_stats[2], h1 = g_stats[3];
    float4 v = *(((const float4*)&g_pre[0][0]) + idx);
    v.x = v.x * s0 + h0;
    v.y = v.y * s1 + h1;
    v.z = v.z * s0 + h0;
    v.w = v.w * s1 + h1;
    ((float4*)out)[idx] = v;
}

// ---------------------------------------------------------------------------
extern "C" void kernel_launch(void* const* d_in, const int* in_sizes, int n_in,
                              void* d_out, int out_size) {
    const float* x     = (const float*)d_in[0];
    const float* w     = (const float*)d_in[1];
    const float* sw    = (const float*)d_in[2];
    const float* sb    = (const float*)d_in[3];
    const float* gamma = (const float*)d_in[4];
    const float* beta  = (const float*)d_in[5];
    const float* grd   = (const float*)d_in[6];
    const float* cay   = (const float*)d_in[7];
    float* out = (float*)d_out;

    static int once = 0;
    if (!once) {
        cudaFuncSetAttribute(k_tc, cudaFuncAttributeMaxDynamicSharedMemorySize, SMEM_TC);
        once = 1;
    }

    k_prep<<<8192, 256>>>(w);
    k_sbsum<<<1, 256>>>(sb);
    k_tc<<<dim3(16, 2, SPLIT), 256, SMEM_TC>>>(x, grd);
    k_combine<<<NCOMB, 256>>>(x, sw, cay);
    k_stats<<<1, 256>>>(gamma, beta);
    k_norm<<<512, 256>>>(out);
}

// round 4
// speedup vs baseline: 4.0042x; 1.2745x over previous
#include <cuda_runtime.h>
#include <cuda_bf16.h>
#include <cstdint>
#include <math.h>

// Shapes
#define BSZ   2048
#define IN    128
#define ON    128
#define DN    2
#define NN    256            // O*D
#define SPLIT 8
#define IPS   (IN / SPLIT)   // 16 i's per k-slice
#define NCOMB2 512

// Scratch (static device arrays -- no allocation)
__device__ float g_part[SPLIT][BSZ][NN];       // 16 MB split-K partials
__device__ float g_pre[BSZ][NN];
__device__ float g_sbsum[NN];
__device__ float g_bstat[NCOMB2][4];
__device__ __nv_bfloat16 g_whi[IN * NN * 64];  // 4 MB, [i][n=(o,x)][k=(u,v)]
__device__ __nv_bfloat16 g_wlo[IN * NN * 64];
__device__ __nv_bfloat16 g_shi[SPLIT * NN * 64];  // silu-branch B, [s][n=(o,z)][k=(ii,y)]
__device__ __nv_bfloat16 g_slo[SPLIT * NN * 64];

// ---------------------------------------------------------------------------
// PTX helpers (sm_80-class ISA only: ldmatrix / mma.sync / cp.async)
// ---------------------------------------------------------------------------
__device__ __forceinline__ uint32_t smem_u32(const void* p) {
    uint32_t a;
    asm("{ .reg .u64 t; cvta.to.shared.u64 t, %1; cvt.u32.u64 %0, t; }" : "=r"(a) : "l"(p));
    return a;
}
__device__ __forceinline__ void ldsm_x4(uint32_t* r, uint32_t addr) {
    asm volatile("ldmatrix.sync.aligned.m8n8.x4.shared.b16 {%0,%1,%2,%3}, [%4];"
                 : "=r"(r[0]), "=r"(r[1]), "=r"(r[2]), "=r"(r[3]) : "r"(addr));
}
__device__ __forceinline__ void mma_bf16(float* c, const uint32_t* a, const uint32_t* b) {
    asm volatile(
        "mma.sync.aligned.m16n8k16.row.col.f32.bf16.bf16.f32 "
        "{%0,%1,%2,%3}, {%4,%5,%6,%7}, {%8,%9}, {%0,%1,%2,%3};"
        : "+f"(c[0]), "+f"(c[1]), "+f"(c[2]), "+f"(c[3])
        : "r"(a[0]), "r"(a[1]), "r"(a[2]), "r"(a[3]), "r"(b[0]), "r"(b[1]));
}
#define CP_ASYNC16(dst, src) asm volatile("cp.async.cg.shared.global [%0], [%1], 16;" :: "r"(dst), "l"(src) : "memory")
#define CP_COMMIT()          asm volatile("cp.async.commit_group;" ::: "memory")
#define CP_WAIT(n)           asm volatile("cp.async.wait_group %0;" :: "n"(n) : "memory")

// smem geometry: rows padded to 72 bf16 (144 B), 128 rows per matrix
#define RPAD   72
#define MAT    (128 * RPAD * 2)            // 18432 B
#define A_HI   0
#define A_LO   MAT
#define B_BASE (2 * MAT)                   // two B buffers of (hi+lo) = 2*MAT each
#define SMEM_TC (2 * MAT + 2 * 2 * MAT)    // 110592 B

// ---------------------------------------------------------------------------
// Prep: split weights into bf16 hi/lo in layout [i][n=(o*2+x)][k=(u*8+v)].
// Vectorized: each thread consumes one float4 of w -> 4 bf16x2 stores.
// ---------------------------------------------------------------------------
__global__ void k_prep(const float* __restrict__ w) {
    int idx4 = blockIdx.x * 256 + threadIdx.x;   // 0 .. 524287
    int flat = idx4 * 4;                          // w flat index, x component = 0
    int i  = flat >> 14;
    int o  = (flat >> 7) & 127;
    int u  = (flat >> 4) & 7;
    int v0 = (flat >> 1) & 7;                     // even
    float4 w4 = *(const float4*)(w + flat);       // (v0,x0)(v0,x1)(v1,x0)(v1,x1)

    int k0 = u * 8 + v0;
    size_t r0 = ((size_t)i * NN + o * 2)     * 64 + k0;  // x=0 row
    size_t r1 = ((size_t)i * NN + o * 2 + 1) * 64 + k0;  // x=1 row

    float a00 = w4.x, a10 = w4.y, a01 = w4.z, a11 = w4.w;
    __nv_bfloat16 h00 = __float2bfloat16(a00), h10 = __float2bfloat16(a10);
    __nv_bfloat16 h01 = __float2bfloat16(a01), h11 = __float2bfloat16(a11);
    __nv_bfloat16 l00 = __float2bfloat16(a00 - __bfloat162float(h00));
    __nv_bfloat16 l10 = __float2bfloat16(a10 - __bfloat162float(h10));
    __nv_bfloat16 l01 = __float2bfloat16(a01 - __bfloat162float(h01));
    __nv_bfloat16 l11 = __float2bfloat16(a11 - __bfloat162float(h11));

    *(__nv_bfloat162*)(g_whi + r0) = __nv_bfloat162(h00, h01);
    *(__nv_bfloat162*)(g_whi + r1) = __nv_bfloat162(h10, h11);
    *(__nv_bfloat162*)(g_wlo + r0) = __nv_bfloat162(l00, l01);
    *(__nv_bfloat162*)(g_wlo + r1) = __nv_bfloat162(l10, l11);
}

// ---------------------------------------------------------------------------
// Prep2: silu-branch B matrix per slice:
//   B[s][(o,z)][(ii,y)] = sum_x sw[s*IPS+ii, o, x] * C[x,y,z]   (k<32; zero-pad to 64)
// Last block (512) computes sbsum[n] = sum_i silu_bias[i][n].
// ---------------------------------------------------------------------------
__global__ void k_prep2(const float* __restrict__ sw, const float* __restrict__ sb,
                        const float* __restrict__ cay) {
    if (blockIdx.x == 512) {
        int n = threadIdx.x;
        float s = 0.f;
        for (int i = 0; i < IN; i++) s += sb[i * NN + n];
        g_sbsum[n] = s;
        return;
    }
    int idx = blockIdx.x * 256 + threadIdx.x;    // 0 .. 131071
    int s = idx >> 14;
    int n = (idx >> 6) & 255;
    int k = idx & 63;
    float val = 0.f;
    if (k < 32) {
        int ii = k >> 1, y = k & 1, o = n >> 1, z = n & 1;
        int i = s * IPS + ii;
        float sw0 = sw[((size_t)i * ON + o) * 2 + 0];
        float sw1 = sw[((size_t)i * ON + o) * 2 + 1];
        val = sw0 * cay[y * 2 + z] + sw1 * cay[4 + y * 2 + z];
    }
    __nv_bfloat16 h = __float2bfloat16(val);
    g_shi[idx] = h;
    g_slo[idx] = __float2bfloat16(val - __bfloat162float(h));
}

// ---------------------------------------------------------------------------
// Tensor-core split-K GEMM via mma.sync. grid (16, 2, SPLIT) = 256 CTAs.
// CTA tile 128(M) x 128(N). Per slice: 16 rbf k-iters (K=64 each) + 1 silu iter.
// A generated on the fly -> bf16 hi/lo smem (single buffer).
// B: cp.async double-buffered. 3-pass split: ah*bh + al*bh + ah*bl.
// ---------------------------------------------------------------------------
__global__ __launch_bounds__(256, 2)
void k_tc(const float* __restrict__ x, const float* __restrict__ grd) {
    extern __shared__ char smdyn[];
    __shared__ float gS[16];

    const int tid = threadIdx.x;
    const int wid = tid >> 5, lid = tid & 31;
    const int bm = blockIdx.x * 128;
    const int n0 = blockIdx.y * 128;
    const int sl = blockIdx.z;
    const int i0 = sl * IPS;

    if (tid < 8) {
        gS[tid]     = grd[tid * 16];       // g[u] (real axis)
        gS[8 + tid] = grd[tid * 2 + 1];    // g[v] (imag axis)
    }

    const uint32_t sbase = smem_u32(smdyn);
    const int wm = wid >> 1, wn = wid & 1;
    const int R = wm * 32, C = wn * 64;

    float acc[2][8][4];
#pragma unroll
    for (int t = 0; t < 2; t++)
#pragma unroll
        for (int j = 0; j < 8; j++)
#pragma unroll
            for (int e = 0; e < 4; e++) acc[t][j][e] = 0.f;

    const int am = tid >> 1;
    const int hh = tid & 1;
    const int u0 = hh * 4;
    const float* xrow = x + (size_t)(bm + am) * (IN * DN);

    // prefetch B for iter 0 into buffer 0
    {
        const __nv_bfloat16* sH = g_whi + ((size_t)i0 * NN + n0) * 64;
        const __nv_bfloat16* sL = g_wlo + ((size_t)i0 * NN + n0) * 64;
#pragma unroll
        for (int c = 0; c < 4; c++) {
            int ch = tid + c * 256;
            uint32_t dst = (uint32_t)((ch >> 3) * (RPAD * 2) + (ch & 7) * 16);
            CP_ASYNC16(sbase + B_BASE + dst,       sH + ch * 8);
            CP_ASYNC16(sbase + B_BASE + MAT + dst, sL + ch * 8);
        }
        CP_COMMIT();
    }
    __syncthreads();   // gS visible

    for (int ii = 0; ii <= IPS; ii++) {
        const uint32_t bufB = sbase + B_BASE + (uint32_t)(ii & 1) * (2 * MAT);

        // ---- A fill (single buffer; prior MMA finished at last __syncthreads) ----
        if (ii < IPS) {
            const int i = i0 + ii;
            float xr = xrow[i * 2], xi = xrow[i * 2 + 1];
            float evr[8], eur[4];
#pragma unroll
            for (int v = 0; v < 8; v++) { float d = xi - gS[8 + v]; evr[v] = __expf(-d * d); }
#pragma unroll
            for (int uu = 0; uu < 4; uu++) { float d = xr - gS[u0 + uu]; eur[uu] = __expf(-d * d); }
#pragma unroll
            for (int uu = 0; uu < 4; uu++) {
                union { __nv_bfloat16 b[8]; uint4 v; } Hi, Lo;
#pragma unroll
                for (int v = 0; v < 8; v++) {
                    float a = eur[uu] * evr[v];
                    __nv_bfloat16 h = __float2bfloat16(a);
                    Hi.b[v] = h;
                    Lo.b[v] = __float2bfloat16(a - __bfloat162float(h));
                }
                uint32_t off = (uint32_t)(am * (RPAD * 2) + (u0 + uu) * 16);
                *(uint4*)(smdyn + A_HI + off) = Hi.v;
                *(uint4*)(smdyn + A_LO + off) = Lo.v;
            }
        } else {
            // silu iteration: k<32 = silu(x[b, i0..i0+16, y]), k>=32 zero
            if (hh == 0) {
                const float* xs = xrow + i0 * 2;   // 32 contiguous floats
#pragma unroll
                for (int c = 0; c < 4; c++) {
                    union { __nv_bfloat16 b[8]; uint4 v; } Hi, Lo;
#pragma unroll
                    for (int e = 0; e < 8; e++) {
                        float v = xs[c * 8 + e];
                        float a = v / (1.f + __expf(-v));
                        __nv_bfloat16 h = __float2bfloat16(a);
                        Hi.b[e] = h;
                        Lo.b[e] = __float2bfloat16(a - __bfloat162float(h));
                    }
                    uint32_t off = (uint32_t)(am * (RPAD * 2) + c * 16);
                    *(uint4*)(smdyn + A_HI + off) = Hi.v;
                    *(uint4*)(smdyn + A_LO + off) = Lo.v;
                }
            } else {
                uint4 z4 = make_uint4(0, 0, 0, 0);
#pragma unroll
                for (int c = 0; c < 4; c++) {
                    uint32_t off = (uint32_t)(am * (RPAD * 2) + (4 + c) * 16);
                    *(uint4*)(smdyn + A_HI + off) = z4;
                    *(uint4*)(smdyn + A_LO + off) = z4;
                }
            }
        }

        // ---- prefetch next B ----
        if (ii < IPS) {
            const __nv_bfloat16 *sH, *sL;
            if (ii + 1 < IPS) {
                sH = g_whi + ((size_t)(i0 + ii + 1) * NN + n0) * 64;
                sL = g_wlo + ((size_t)(i0 + ii + 1) * NN + n0) * 64;
            } else {
                sH = g_shi + ((size_t)sl * NN + n0) * 64;
                sL = g_slo + ((size_t)sl * NN + n0) * 64;
            }
            uint32_t nb = sbase + B_BASE + (uint32_t)((ii + 1) & 1) * (2 * MAT);
#pragma unroll
            for (int c = 0; c < 4; c++) {
                int ch = tid + c * 256;
                uint32_t dst = (uint32_t)((ch >> 3) * (RPAD * 2) + (ch & 7) * 16);
                CP_ASYNC16(nb + dst,       sH + ch * 8);
                CP_ASYNC16(nb + MAT + dst, sL + ch * 8);
            }
            CP_COMMIT();
            CP_WAIT(1);
        } else {
            CP_WAIT(0);
        }
        __syncthreads();

        // ---- MMA over K=64: 4 k-steps, 3 split passes ----
#pragma unroll
        for (int ks = 0; ks < 4; ks++) {
            uint32_t ah[2][4], al[2][4];
#pragma unroll
            for (int t = 0; t < 2; t++) {
                int row = R + t * 16 + (lid & 15);
                uint32_t cb = (uint32_t)(ks * 32 + (lid >> 4) * 16);
                uint32_t aoff = (uint32_t)(row * (RPAD * 2)) + cb;
                ldsm_x4(ah[t], sbase + A_HI + aoff);
                ldsm_x4(al[t], sbase + A_LO + aoff);
            }
#pragma unroll
            for (int jj = 0; jj < 4; jj++) {
                int nrow = C + jj * 16 + ((lid >> 4) * 8) + (lid & 7);
                uint32_t cb = (uint32_t)(ks * 32 + ((lid >> 3) & 1) * 16);
                uint32_t boff = (uint32_t)(nrow * (RPAD * 2)) + cb;
                uint32_t bh[4], bl[4];
                ldsm_x4(bh, bufB + boff);
                ldsm_x4(bl, bufB + MAT + boff);
#pragma unroll
                for (int t = 0; t < 2; t++) {
                    mma_bf16(acc[t][jj * 2],     ah[t], bh);
                    mma_bf16(acc[t][jj * 2],     al[t], bh);
                    mma_bf16(acc[t][jj * 2],     ah[t], bl);
                    mma_bf16(acc[t][jj * 2 + 1], ah[t], bh + 2);
                    mma_bf16(acc[t][jj * 2 + 1], al[t], bh + 2);
                    mma_bf16(acc[t][jj * 2 + 1], ah[t], bl + 2);
                }
            }
        }
        __syncthreads();
    }

    // ---- epilogue: registers -> split-K partials ----
#pragma unroll
    for (int t = 0; t < 2; t++) {
#pragma unroll
        for (int j = 0; j < 8; j++) {
            int row = bm + R + t * 16 + (lid >> 2);
            int col = n0 + C + j * 8 + (lid & 3) * 2;
            *(float2*)&g_part[sl][row][col]     = make_float2(acc[t][j][0], acc[t][j][1]);
            *(float2*)&g_part[sl][row + 8][col] = make_float2(acc[t][j][2], acc[t][j][3]);
        }
    }
}

// ---------------------------------------------------------------------------
// Combine: pure streaming partial-sum + per-CTA BN stats. grid 512 x 256.
// ---------------------------------------------------------------------------
__global__ __launch_bounds__(256)
void k_combine() {
    __shared__ float rs[256], rq[256], rs1[256], rq1[256];
    const int tid = threadIdx.x;
    const int idx = blockIdx.x * 256 + tid;    // float4 id, 131072 total

    float4 v = ((const float4*)g_sbsum)[idx & 63];
    const float4* pp = (const float4*)g_part;
#pragma unroll
    for (int s = 0; s < SPLIT; s++) {
        float4 p = pp[(size_t)s * 131072 + idx];
        v.x += p.x; v.y += p.y; v.z += p.z; v.w += p.w;
    }
    ((float4*)g_pre)[idx] = v;

    rs[tid]  = v.x + v.z;          // component 0 sums
    rs1[tid] = v.y + v.w;          // component 1
    rq[tid]  = v.x * v.x + v.z * v.z;
    rq1[tid] = v.y * v.y + v.w * v.w;
    __syncthreads();
    for (int st = 128; st >= 1; st >>= 1) {
        if (tid < st) {
            rs[tid] += rs[tid + st];  rs1[tid] += rs1[tid + st];
            rq[tid] += rq[tid + st];  rq1[tid] += rq1[tid + st];
        }
        __syncthreads();
    }
    if (tid == 0) {
        g_bstat[blockIdx.x][0] = rs[0];
        g_bstat[blockIdx.x][1] = rs1[0];
        g_bstat[blockIdx.x][2] = rq[0];
        g_bstat[blockIdx.x][3] = rq1[0];
    }
}

// ---------------------------------------------------------------------------
// Norm: each CTA redundantly reduces g_bstat (512x4), then normalizes its slice.
// ---------------------------------------------------------------------------
__global__ __launch_bounds__(256)
void k_norm(const float* __restrict__ gamma, const float* __restrict__ beta,
            float* __restrict__ out) {
    __shared__ float r[4][256];
    __shared__ float st[4];
    const int tid = threadIdx.x;
#pragma unroll
    for (int j = 0; j < 4; j++)
        r[j][tid] = g_bstat[tid][j] + g_bstat[tid + 256][j];
    __syncthreads();
    for (int s = 128; s >= 1; s >>= 1) {
        if (tid < s) {
#pragma unroll
            for (int j = 0; j < 4; j++) r[j][tid] += r[j][tid + s];
        }
        __syncthreads();
    }
    if (tid < 2) {
        const float Ninv = 1.f / (2048.f * 128.f);
        float mean = r[tid][0] * Ninv;
        float var  = r[2 + tid][0] * Ninv - mean * mean;
        float sc   = gamma[tid] * rsqrtf(var + 1e-5f);
        st[tid]     = sc;
        st[2 + tid] = beta[tid] - mean * sc;
    }
    __syncthreads();

    int idx = blockIdx.x * 256 + tid;
    float s0 = st[0], s1 = st[1], h0 = st[2], h1 = st[3];
    float4 v = ((const float4*)g_pre)[idx];
    v.x = v.x * s0 + h0;
    v.y = v.y * s1 + h1;
    v.z = v.z * s0 + h0;
    v.w = v.w * s1 + h1;
    ((float4*)out)[idx] = v;
}

// ---------------------------------------------------------------------------
extern "C" void kernel_launch(void* const* d_in, const int* in_sizes, int n_in,
                              void* d_out, int out_size) {
    const float* x     = (const float*)d_in[0];
    const float* w     = (const float*)d_in[1];
    const float* sw    = (const float*)d_in[2];
    const float* sb    = (const float*)d_in[3];
    const float* gamma = (const float*)d_in[4];
    const float* beta  = (const float*)d_in[5];
    const float* grd   = (const float*)d_in[6];
    const float* cay   = (const float*)d_in[7];
    float* out = (float*)d_out;

    static int once = 0;
    if (!once) {
        cudaFuncSetAttribute(k_tc, cudaFuncAttributeMaxDynamicSharedMemorySize, SMEM_TC);
        once = 1;
    }

    k_prep<<<2048, 256>>>(w);
    k_prep2<<<513, 256>>>(sw, sb, cay);
    k_tc<<<dim3(16, 2, SPLIT), 256, SMEM_TC>>>(x, grd);
    k_combine<<<512, 256>>>();
    k_norm<<<512, 256>>>(gamma, beta, out);
}